// round 1
// baseline (speedup 1.0000x reference)
#include <cuda_runtime.h>

// Problem constants (fixed by the reference)
#define MUL  16
#define DD   4
#define S0N  8
#define S1N  8
#define SOUTN 8
#define P3N  8
#define P4N  4

constexpr int EPB     = 8;    // edges per block
constexpr int THREADS = 128;  // 16 threads (one per u) x 8 edges
constexpr int ES      = 240;  // per-edge scratch stride in floats (16B aligned, bank-offset 16 between groups)
// per-edge scratch layout: [0,32) x1 row; [32,160) W3[p][i][k]; [160,224) W4[p][i][m]

__global__ __launch_bounds__(THREADS, 8)
void tp_kernel(const float* __restrict__ x0,
               const int*   __restrict__ i0,
               const float* __restrict__ x1,
               const float* __restrict__ C3,
               const float* __restrict__ C4,
               const int*   __restrict__ p3,
               const int*   __restrict__ p4,
               float* __restrict__ out,
               int E, int nBatch)
{
    // C3 staged with i-row stride 20 (banks: 20*i mod 32 in {0,20,8,28} -> conflict-free for (i,k) lanes)
    __shared__ float sC3[P3N * 80];
    // C4 staged with i-row stride 68 (banks: 4*i + m distinct for all 16 (i,m) lanes)
    __shared__ float sC4[P4N * 272];
    __shared__ int   sp3[P3N * 3];
    __shared__ int   sp4[P4N * 4];
    __shared__ int   sCnt[SOUTN];
    __shared__ int   sList[SOUTN][P3N + P4N];   // packed: (wOffset << 8) | s0
    __shared__ __align__(16) float sEdge[EPB][ES];

    const int tid = threadIdx.x;

    // ---- stage constants (once per block) ----
    for (int idx = tid; idx < 512; idx += THREADS) {
        int p = idx >> 6, i = (idx >> 4) & 3, r = idx & 15;   // r = j*4+k
        sC3[p * 80 + i * 20 + r] = C3[idx];
    }
    for (int idx = tid; idx < 1024; idx += THREADS) {
        int p = idx >> 8, i = (idx >> 6) & 3, r = idx & 63;   // r = (j*4+k)*4+m
        sC4[p * 272 + i * 68 + r] = C4[idx];
    }
    if (tid < P3N * 3) sp3[tid] = p3[tid];
    if (tid < P4N * 4) sp4[tid] = p4[tid];
    __syncthreads();

    // ---- build per-output-segment contribution lists (avoids dynamic register indexing) ----
    if (tid == 0) {
        for (int so = 0; so < SOUTN; so++) {
            int c = 0;
            for (int p = 0; p < P3N; p++)
                if (sp3[p * 3 + 2] == so)
                    sList[so][c++] = ((32 + p * 16) << 8) | sp3[p * 3 + 0];
            for (int p = 0; p < P4N; p++)
                if (sp4[p * 4 + 3] == so)
                    sList[so][c++] = ((160 + p * 16) << 8) | sp4[p * 4 + 0];
            sCnt[so] = c;
        }
    }
    __syncthreads();

    const int g = tid >> 4;   // edge slot within block (0..7)
    const int u = tid & 15;   // MUL index
    float* eg = sEdge[g];

    for (int batch = blockIdx.x; batch < nBatch; batch += gridDim.x) {
        const long long e = (long long)batch * EPB + g;
        const bool active = (e < E);

        __syncwarp();   // previous iteration's readers done before overwriting scratch

        // ---- stage x1 row (32 floats, 2 per thread, coalesced) ----
        if (active) {
            const float2 v = *reinterpret_cast<const float2*>(x1 + e * 32 + u * 2);
            *reinterpret_cast<float2*>(eg + u * 2) = v;
        }
        __syncwarp();

        // ---- W3[p][i][k] = sum_j b[j] * C3[p][i][j][k] ; lane u = (i,k) ----
        {
            const int i = u >> 2, k = u & 3;
            #pragma unroll
            for (int p = 0; p < P3N; p++) {
                const int seg = sp3[p * 3 + 1];
                const float* b = eg + seg * 4;                  // broadcast within group
                const float* c = sC3 + p * 80 + i * 20 + k;     // conflict-free lanes
                float w = b[0]*c[0] + b[1]*c[4] + b[2]*c[8] + b[3]*c[12];
                eg[32 + p * 16 + u] = w;                        // u == i*4+k
            }
        }
        // ---- W4[p][i][m] = sum_{j,k} b[j] c[k] * C4[p][i][j][k][m] ; lane u = (i,m) ----
        {
            const int i = u >> 2, m = u & 3;
            #pragma unroll
            for (int p = 0; p < P4N; p++) {
                const float* b = eg + sp4[p * 4 + 1] * 4;
                const float* c = eg + sp4[p * 4 + 2] * 4;
                const float* q = sC4 + p * 272 + i * 68 + m;    // conflict-free lanes
                float w = 0.f;
                #pragma unroll
                for (int j = 0; j < 4; j++) {
                    const float bj = b[j];
                    #pragma unroll
                    for (int k = 0; k < 4; k++)
                        w += bj * c[k] * q[(j * 4 + k) * 4];
                }
                eg[160 + p * 16 + u] = w;                       // u == i*4+m
            }
        }
        __syncwarp();

        // ---- main contraction: out[so][u][:] = sum over entries a[s0][u][:] @ W(4x4) ----
        if (active) {
            const long long xrow = (long long)__ldg(i0 + e) * 512 + u * 4;
            float* op = out + e * 512 + u * 4;
            #pragma unroll
            for (int so = 0; so < SOUTN; so++) {
                float4 acc = make_float4(0.f, 0.f, 0.f, 0.f);
                const int n = sCnt[so];
                for (int t = 0; t < n; t++) {                   // uniform across warp -> no divergence
                    const int ent = sList[so][t];
                    const int s0  = ent & 0xFF;
                    const int wo  = ent >> 8;
                    const float4 av = __ldg(reinterpret_cast<const float4*>(x0 + xrow + s0 * 64));
                    const float4 w0 = *reinterpret_cast<const float4*>(eg + wo);
                    const float4 w1 = *reinterpret_cast<const float4*>(eg + wo + 4);
                    const float4 w2 = *reinterpret_cast<const float4*>(eg + wo + 8);
                    const float4 w3 = *reinterpret_cast<const float4*>(eg + wo + 12);
                    acc.x += av.x*w0.x + av.y*w1.x + av.z*w2.x + av.w*w3.x;
                    acc.y += av.x*w0.y + av.y*w1.y + av.z*w2.y + av.w*w3.y;
                    acc.z += av.x*w0.z + av.y*w1.z + av.z*w2.z + av.w*w3.z;
                    acc.w += av.x*w0.w + av.y*w1.w + av.z*w2.w + av.w*w3.w;
                }
                *reinterpret_cast<float4*>(op + so * 64) = acc; // coalesced 256B per group
            }
        }
    }
}

extern "C" void kernel_launch(void* const* d_in, const int* in_sizes, int n_in,
                              void* d_out, int out_size)
{
    const float* x0 = (const float*)d_in[0];
    const int*   i0 = (const int*)  d_in[1];
    const float* x1 = (const float*)d_in[2];
    const float* C3 = (const float*)d_in[3];
    const float* C4 = (const float*)d_in[4];
    const int*   p3 = (const int*)  d_in[5];
    const int*   p4 = (const int*)  d_in[6];
    float* out = (float*)d_out;

    const int E = in_sizes[1];                    // i0 element count = number of edges
    const int nBatch = (E + EPB - 1) / EPB;
    int grid = nBatch < 4624 ? nBatch : 4624;     // grid-stride to amortize constant staging
    tp_kernel<<<grid, THREADS>>>(x0, i0, x1, C3, C4, p3, p4, out, E, nBatch);
}

// round 2
// speedup vs baseline: 1.0184x; 1.0184x over previous
#include <cuda_runtime.h>

// Problem constants (fixed by the reference)
#define MUL  16
#define DD   4
#define S0N  8
#define S1N  8
#define SOUTN 8
#define P3N  8
#define P4N  4

constexpr int EPB     = 8;    // edges per block
constexpr int THREADS = 128;  // 16 threads (one per u) x 8 edges
constexpr int ES      = 240;  // per-edge scratch stride in floats (16B aligned)
// per-edge scratch layout: [0,32) x1 row; [32,160) W3[p][i][k]; [160,224) W4[p][i][m]

__global__ __launch_bounds__(THREADS, 8)
void tp_kernel(const float* __restrict__ x0,
               const int*   __restrict__ i0,
               const float* __restrict__ x1,
               const float* __restrict__ C3,
               const float* __restrict__ C4,
               const int*   __restrict__ p3,
               const int*   __restrict__ p4,
               float* __restrict__ out,
               int E, int nBatch)
{
    // Transposed C3: sC3T[p*64 + (i*4+k)*4 + j]  -> lane (i,k) reads its 4 j-values as one float4.
    // 16 lanes x 16B distinct data = 256B -> 2 wavefronts (minimum).
    __shared__ __align__(16) float sC3T[P3N * 64];
    // Transposed C4: sC4T[p*320 + (i*4+m)*20 + j*4 + k] -> lane (i,m) reads 4 float4 (j-rows).
    // 20-word lane stride: bank quad start (20u+4c) mod 32 distinct for lanes 0-7 -> 2 wf per LDS.128.
    __shared__ __align__(16) float sC4T[P4N * 320];
    __shared__ int   sp3[P3N * 3];
    __shared__ int   sp4[P4N * 4];
    __shared__ int   sCnt[SOUTN];
    __shared__ int   sList[SOUTN][P3N + P4N];   // packed: (wOffset << 8) | s0
    __shared__ __align__(16) float sEdge[EPB][ES];

    const int tid = threadIdx.x;

    // ---- stage constants (once per block), transposing for vector loads ----
    for (int idx = tid; idx < 512; idx += THREADS) {
        int p = idx >> 6, r = idx & 63;
        int i = r >> 4, j = (r >> 2) & 3, k = r & 3;
        sC3T[p * 64 + (i * 4 + k) * 4 + j] = C3[idx];
    }
    for (int idx = tid; idx < 1024; idx += THREADS) {
        int p = idx >> 8, r = idx & 255;
        int i = r >> 6, j = (r >> 4) & 3, k = (r >> 2) & 3, m = r & 3;
        sC4T[p * 320 + (i * 4 + m) * 20 + j * 4 + k] = C4[idx];
    }
    if (tid < P3N * 3) sp3[tid] = p3[tid];
    if (tid < P4N * 4) sp4[tid] = p4[tid];
    __syncthreads();

    // ---- build per-output-segment contribution lists (avoids dynamic register indexing) ----
    if (tid == 0) {
        for (int so = 0; so < SOUTN; so++) {
            int c = 0;
            for (int p = 0; p < P3N; p++)
                if (sp3[p * 3 + 2] == so)
                    sList[so][c++] = ((32 + p * 16) << 8) | sp3[p * 3 + 0];
            for (int p = 0; p < P4N; p++)
                if (sp4[p * 4 + 3] == so)
                    sList[so][c++] = ((160 + p * 16) << 8) | sp4[p * 4 + 0];
            sCnt[so] = c;
        }
    }
    __syncthreads();

    const int g = tid >> 4;   // edge slot within block (0..7)
    const int u = tid & 15;   // MUL index (also (i,k)/(i,m) in W-build)
    float* eg = sEdge[g];

    for (int batch = blockIdx.x; batch < nBatch; batch += gridDim.x) {
        const long long e = (long long)batch * EPB + g;
        const bool active = (e < E);

        __syncwarp();   // previous iteration's readers done before overwriting scratch

        // ---- stage x1 row (32 floats, 2 per thread, coalesced) ----
        if (active) {
            const float2 v = *reinterpret_cast<const float2*>(x1 + e * 32 + u * 2);
            *reinterpret_cast<float2*>(eg + u * 2) = v;
        }
        __syncwarp();

        // ---- W3[p][i][k] = sum_j b[j] * C3[p][i][j][k] ; lane u = (i,k) ----
        #pragma unroll
        for (int p = 0; p < P3N; p++) {
            const int seg = sp3[p * 3 + 1];
            const float4 b = *reinterpret_cast<const float4*>(eg + seg * 4);
            const float4 c = *reinterpret_cast<const float4*>(sC3T + p * 64 + u * 4);
            eg[32 + p * 16 + u] = b.x * c.x + b.y * c.y + b.z * c.z + b.w * c.w;
        }
        // ---- W4[p][i][m] = sum_{j,k} b[j] c[k] * C4[p][i][j][k][m] ; lane u = (i,m) ----
        #pragma unroll
        for (int p = 0; p < P4N; p++) {
            const float4 b = *reinterpret_cast<const float4*>(eg + sp4[p * 4 + 1] * 4);
            const float4 c = *reinterpret_cast<const float4*>(eg + sp4[p * 4 + 2] * 4);
            const float* q = sC4T + p * 320 + u * 20;
            const float4 q0 = *reinterpret_cast<const float4*>(q);
            const float4 q1 = *reinterpret_cast<const float4*>(q + 4);
            const float4 q2 = *reinterpret_cast<const float4*>(q + 8);
            const float4 q3 = *reinterpret_cast<const float4*>(q + 12);
            float w = b.x * (c.x * q0.x + c.y * q0.y + c.z * q0.z + c.w * q0.w);
            w      += b.y * (c.x * q1.x + c.y * q1.y + c.z * q1.z + c.w * q1.w);
            w      += b.z * (c.x * q2.x + c.y * q2.y + c.z * q2.z + c.w * q2.w);
            w      += b.w * (c.x * q3.x + c.y * q3.y + c.z * q3.z + c.w * q3.w);
            eg[160 + p * 16 + u] = w;
        }
        __syncwarp();

        // ---- main contraction: out[so][u][:] = sum over entries a[s0][u][:] @ W(4x4) ----
        if (active) {
            const long long xrow = (long long)__ldg(i0 + e) * 512 + u * 4;
            float* op = out + e * 512 + u * 4;
            #pragma unroll
            for (int so = 0; so < SOUTN; so++) {
                float4 acc = make_float4(0.f, 0.f, 0.f, 0.f);
                const int n = sCnt[so];
                for (int t = 0; t < n; t++) {                   // uniform across warp -> no divergence
                    const int ent = sList[so][t];
                    const int s0  = ent & 0xFF;
                    const int wo  = ent >> 8;
                    const float4 av = __ldg(reinterpret_cast<const float4*>(x0 + xrow + s0 * 64));
                    const float4 w0 = *reinterpret_cast<const float4*>(eg + wo);
                    const float4 w1 = *reinterpret_cast<const float4*>(eg + wo + 4);
                    const float4 w2 = *reinterpret_cast<const float4*>(eg + wo + 8);
                    const float4 w3 = *reinterpret_cast<const float4*>(eg + wo + 12);
                    acc.x += av.x*w0.x + av.y*w1.x + av.z*w2.x + av.w*w3.x;
                    acc.y += av.x*w0.y + av.y*w1.y + av.z*w2.y + av.w*w3.y;
                    acc.z += av.x*w0.z + av.y*w1.z + av.z*w2.z + av.w*w3.z;
                    acc.w += av.x*w0.w + av.y*w1.w + av.z*w2.w + av.w*w3.w;
                }
                // streaming store: keep the 204MB output stream from evicting x0 in L2
                __stcs(reinterpret_cast<float4*>(op + so * 64), acc);
            }
        }
    }
}

extern "C" void kernel_launch(void* const* d_in, const int* in_sizes, int n_in,
                              void* d_out, int out_size)
{
    const float* x0 = (const float*)d_in[0];
    const int*   i0 = (const int*)  d_in[1];
    const float* x1 = (const float*)d_in[2];
    const float* C3 = (const float*)d_in[3];
    const float* C4 = (const float*)d_in[4];
    const int*   p3 = (const int*)  d_in[5];
    const int*   p4 = (const int*)  d_in[6];
    float* out = (float*)d_out;

    const int E = in_sizes[1];                    // i0 element count = number of edges
    const int nBatch = (E + EPB - 1) / EPB;
    int grid = nBatch < 4624 ? nBatch : 4624;     // grid-stride to amortize constant staging
    tp_kernel<<<grid, THREADS>>>(x0, i0, x1, C3, C4, p3, p4, out, E, nBatch);
}